// round 7
// baseline (speedup 1.0000x reference)
#include <cuda_runtime.h>

typedef unsigned long long ull;

#define OUT_KNN   2097152u
#define OUT_LOCAL 35651584u

__device__ int   g_idx[8 * 2048 * 16];
__device__ float g_h[16384 * 128];
__device__ float g_z[16384 * 128];

// Distance matching the reference lowering:
//   sq  = (x*x + y*y) + z*z            (separate roundings, HLO mul+reduce)
//   dot = fma(z,z', fma(y,y', x*x'))   (K=3 gemm accumulator chain, c-order)
//   d2  = (sq_i + sq_j) - 2*dot        (each HLO op rounded separately)
__device__ __forceinline__ float d2_of(float4 a, float4 b) {
    float dot = __fmaf_rn(a.z, b.z, __fmaf_rn(a.y, b.y, __fmul_rn(a.x, b.x)));
    return __fsub_rn(__fadd_rn(a.w, b.w), __fmul_rn(2.0f, dot));
}

__device__ __forceinline__ ull fma2(ull a, ull b, ull c) {
    ull d;
    asm("fma.rn.f32x2 %0,%1,%2,%3;" : "=l"(d) : "l"(a), "l"(b), "l"(c));
    return d;
}

// ---------------------------------------------------------------------------
// K1: exact top-16 KNN (stable ties), split-j halves + merge; writes g_idx
//     and local_coords.
// ---------------------------------------------------------------------------
__global__ __launch_bounds__(128) void knn_kernel(const float* __restrict__ coords,
                                                  float* __restrict__ out)
{
    __shared__ float4 cs[2048];
    __shared__ float  md[64 * 16];
    __shared__ int    mi[64 * 16];

    const int t = threadIdx.x, q = t & 63, hf = t >> 6;
    const int b = blockIdx.y;
    const int i = blockIdx.x * 64 + q;
    const float* cb = coords + (size_t)b * 3 * 2048;

    for (int j = t; j < 2048; j += 128) {
        float X = cb[j], Y = cb[2048 + j], Z = cb[4096 + j];
        float s = __fadd_rn(__fadd_rn(__fmul_rn(X, X), __fmul_rn(Y, Y)), __fmul_rn(Z, Z));
        cs[j] = make_float4(X, Y, Z, s);
    }
    __syncthreads();

    const float4 ci = cs[i];
    const float INF = __int_as_float(0x7f800000);
    const int jbeg = hf << 10, jend = jbeg + 1024;

    // Pass 1: value-only sorted-16 (exact running 16th smallest) + candidate log
    float vt[16];
#pragma unroll
    for (int s = 0; s < 16; s++) vt[s] = INF;
    unsigned short buf[128];
    int cnt = 0;

#pragma unroll 2
    for (int j = jbeg; j < jend; j++) {
        float d2 = d2_of(ci, cs[j]);
        if (d2 <= vt[15]) {
            buf[cnt & 127] = (unsigned short)j;
            cnt++;
            float c = d2;
#pragma unroll
            for (int s = 0; s < 16; s++) {
                float lo = fminf(c, vt[s]);
                c = fmaxf(c, vt[s]);
                vt[s] = lo;
            }
        }
    }
    const float thr = vt[15];
    (void)thr;

    // Pass 2: replay with payload, lexicographic (d2, j)
    float dd[16]; int nb[16];
#pragma unroll
    for (int s = 0; s < 16; s++) { dd[s] = INF; nb[s] = 0x7fffffff; }

    const int m = (cnt <= 128) ? cnt : 1024;
    for (int e = 0; e < m; e++) {
        int j = (cnt <= 128) ? (int)buf[e] : (jbeg + e);
        float d2 = d2_of(ci, cs[j]);
        if (d2 < dd[15] || (d2 == dd[15] && j < nb[15])) {
            float cd = d2; int cj = j;
#pragma unroll
            for (int s = 0; s < 16; s++) {
                bool lt = (cd < dd[s]) || (cd == dd[s] && cj < nb[s]);
                float nd = lt ? cd : dd[s];
                int   ni = lt ? cj : nb[s];
                cd = lt ? dd[s] : cd; cj = lt ? nb[s] : cj;
                dd[s] = nd; nb[s] = ni;
            }
        }
    }

    if (hf) {
#pragma unroll
        for (int s = 0; s < 16; s++) { md[q * 16 + s] = dd[s]; mi[q * 16 + s] = nb[s]; }
    }
    __syncthreads();
    if (hf) return;

    // Merge two sorted 16-lists (ia+ib = s <= 15, always in range)
    int ia = 0, ib = 0, fi[16];
#pragma unroll
    for (int s = 0; s < 16; s++) {
        float da = dd[ia], db = md[q * 16 + ib];
        int ja = nb[ia], jb = mi[q * 16 + ib];
        bool ta = (da < db) || (da == db && ja < jb);
        fi[s] = ta ? ja : jb;
        ia += ta; ib += !ta;
    }

    int* ip = &g_idx[(size_t)(b * 2048 + i) * 16];
#pragma unroll
    for (int s = 0; s < 16; s++) ip[s] = fi[s];

#pragma unroll
    for (int d = 0; d < 3; d++) {
        float cv = d == 0 ? ci.x : (d == 1 ? ci.y : ci.z);
        float* L = out + OUT_LOCAL + ((size_t)(b * 3 + d) * 2048 + i) * 16;
#pragma unroll
        for (int s = 0; s < 16; s++) {
            float4 cn = cs[fi[s]];
            float nv = d == 0 ? cn.x : (d == 1 ? cn.y : cn.z);
            L[s] = __fsub_rn(cv, nv);
        }
    }
}

// ---------------------------------------------------------------------------
// K2a/K2b: per-point MLP layers on the f32x2 pipe.
// Thread t = output channel o; block handles 64 points.
// ---------------------------------------------------------------------------
__global__ __launch_bounds__(128) void layer1_kernel(const float* __restrict__ x,
                                                     const float* __restrict__ w1,
                                                     const float* __restrict__ g1,
                                                     const float* __restrict__ b1,
                                                     const float* __restrict__ m1,
                                                     const float* __restrict__ v1)
{
    __shared__ float xs[64 * 66];            // [p][c], stride 66 (8B-aligned pairs)
    const int t = threadIdx.x;
    const int P0 = blockIdx.x * 64;
    const int b = P0 >> 11, pl0 = P0 & 2047;
    const float* base = x + (size_t)b * 64 * 2048 + pl0;

    for (int e = t; e < 64 * 64; e += 128) {
        int c = e >> 6, p = e & 63;
        xs[p * 66 + c] = base[c * 2048 + p];
    }
    const float iv = g1[t] / sqrtf(v1[t] + 1e-5f);
    const float cc = b1[t] - m1[t] * iv;

    ull wp[32];
    const ull* wr = (const ull*)(w1 + t * 64);
#pragma unroll
    for (int c2 = 0; c2 < 32; c2++) wp[c2] = wr[c2];
    __syncthreads();

    float* dst = g_h + (size_t)P0 * 128 + t;
#pragma unroll 2
    for (int p = 0; p < 64; p++) {
        ull a0 = 0, a1 = 0;
        const ull* xp = (const ull*)(xs + p * 66);
#pragma unroll
        for (int c2 = 0; c2 < 32; c2 += 2) {
            a0 = fma2(wp[c2], xp[c2], a0);
            a1 = fma2(wp[c2 + 1], xp[c2 + 1], a1);
        }
        float s = __uint_as_float((unsigned)a0) + __uint_as_float((unsigned)(a0 >> 32))
                + __uint_as_float((unsigned)a1) + __uint_as_float((unsigned)(a1 >> 32));
        dst[p * 128] = fmaxf(s * iv + cc, 0.0f);
    }
}

__global__ __launch_bounds__(128) void layer2_kernel(const float* __restrict__ w2,
                                                     const float* __restrict__ g2,
                                                     const float* __restrict__ b2,
                                                     const float* __restrict__ m2,
                                                     const float* __restrict__ v2)
{
    __shared__ float xs[64 * 128];           // [p][c]
    const int t = threadIdx.x;
    const int P0 = blockIdx.x * 64;
    const float* base = g_h + (size_t)P0 * 128;

    for (int e = t; e < 64 * 128; e += 128) xs[e] = base[e];

    const float iv = g2[t] / sqrtf(v2[t] + 1e-5f);
    const float cc = b2[t] - m2[t] * iv;

    ull wp[64];
    const ull* wr = (const ull*)(w2 + t * 128);
#pragma unroll
    for (int c2 = 0; c2 < 64; c2++) wp[c2] = wr[c2];
    __syncthreads();

    float* dst = g_z + (size_t)P0 * 128 + t;
#pragma unroll 2
    for (int p = 0; p < 64; p++) {
        ull a0 = 0, a1 = 0;
        const ull* xp = (const ull*)(xs + p * 128);
#pragma unroll
        for (int c2 = 0; c2 < 64; c2 += 2) {
            a0 = fma2(wp[c2], xp[c2], a0);
            a1 = fma2(wp[c2 + 1], xp[c2 + 1], a1);
        }
        float s = __uint_as_float((unsigned)a0) + __uint_as_float((unsigned)(a0 >> 32))
                + __uint_as_float((unsigned)a1) + __uint_as_float((unsigned)(a1 >> 32));
        dst[p * 128] = fmaxf(s * iv + cc, 0.0f);
    }
}

// ---------------------------------------------------------------------------
// K3: gather z rows through smem transpose; write knn_mlp_x (coalesced) and y.
// Warp handles 2 queries (32 (i,k) pairs). Block = 2 warps = 4 queries.
// ---------------------------------------------------------------------------
__global__ __launch_bounds__(64) void gather_kernel(float* __restrict__ out)
{
    __shared__ float sm[2][32 * 129];
    const int t = threadIdx.x, w = t >> 5, l = t & 31;
    const int Q0 = blockIdx.x * 4;
    const int qg = Q0 + w * 2 + (l >> 4);    // global query (b*2048+i)
    const int b = qg >> 11, i = qg & 2047;
    const int k = l & 15;

    const int jl = g_idx[(size_t)qg * 16 + k];
    const int gr = b * 2048 + jl;            // global z row

    float* S = sm[w];
    for (int r = 0; r < 32; r++) {
        int row = __shfl_sync(0xffffffffu, gr, r);
        const float* zr = g_z + (size_t)row * 128;
#pragma unroll
        for (int u = 0; u < 4; u++)
            S[r * 129 + u * 32 + l] = zr[u * 32 + l];
    }
    __syncwarp();

    const int i0 = (Q0 + w * 2) & 2047;
    for (int o = 0; o < 128; o++) {
        float v = S[l * 129 + o];
        float m = v;
#pragma unroll
        for (int off = 8; off >= 1; off >>= 1)
            m = fmaxf(m, __shfl_xor_sync(0xffffffffu, m, off));
        out[OUT_KNN + ((size_t)(b * 128 + o) * 2048 + i0) * 16 + l] = v;
        if (k == 0)
            out[(size_t)(b * 128 + o) * 2048 + i] = m;
    }
}

extern "C" void kernel_launch(void* const* d_in, const int* in_sizes, int n_in,
                              void* d_out, int out_size)
{
    const float* x      = (const float*)d_in[0];
    const float* coords = (const float*)d_in[1];
    const float* w1     = (const float*)d_in[2];
    const float* g1     = (const float*)d_in[3];
    const float* b1     = (const float*)d_in[4];
    const float* m1     = (const float*)d_in[5];
    const float* v1     = (const float*)d_in[6];
    const float* w2     = (const float*)d_in[7];
    const float* g2     = (const float*)d_in[8];
    const float* b2     = (const float*)d_in[9];
    const float* m2     = (const float*)d_in[10];
    const float* v2     = (const float*)d_in[11];
    float* out = (float*)d_out;

    knn_kernel<<<dim3(32, 8), 128>>>(coords, out);
    layer1_kernel<<<256, 128>>>(x, w1, g1, b1, m1, v1);
    layer2_kernel<<<256, 128>>>(w2, g2, b2, m2, v2);
    gather_kernel<<<4096, 64>>>(out);
}